// round 14
// baseline (speedup 1.0000x reference)
#include <cuda_runtime.h>
#include <cuda_bf16.h>
#include <cstdint>

#define BATCH 8
#define CIN   32
#define COUT  64
#define HW    (512 * 512)
#define NPIX  (BATCH * HW)
#define TILE  128
#define NT    256

#define XPITCHB 528        // x rows: 132 floats; frag LDS bank = 8t+g, all distinct
#define WPITCHB 96         // W rows: pair-interleaved; LDS.64 banks distinct per phase

// smem byte offsets
#define XS_OFF  0                      // 32 * 528 = 16896
#define WHI_OFF 16896                  // 64 * 96 = 6144
#define WLO_OFF (WHI_OFF + 6144)
#define BS_OFF  (WLO_OFF + 6144)       // 256
#define SMEM_TOT (BS_OFF + 256)        // 29440 < 48KB static

__device__ __forceinline__ void mma16816(float* c, const uint32_t* a, const uint32_t* b) {
    asm volatile(
        "mma.sync.aligned.m16n8k16.row.col.f32.bf16.bf16.f32 "
        "{%0,%1,%2,%3}, {%4,%5,%6,%7}, {%8,%9}, {%0,%1,%2,%3};"
        : "+f"(c[0]), "+f"(c[1]), "+f"(c[2]), "+f"(c[3])
        : "r"(a[0]), "r"(a[1]), "r"(a[2]), "r"(a[3]), "r"(b[0]), "r"(b[1]));
}

__device__ __forceinline__ uint32_t pack_bf16(__nv_bfloat16 e0, __nv_bfloat16 e1) {
    __nv_bfloat162 v; v.x = e0; v.y = e1;
    return *(uint32_t*)&v;
}
__device__ __forceinline__ uint32_t pack_hi(float a, float b) {
    return pack_bf16(__float2bfloat16(a), __float2bfloat16(b));
}
__device__ __forceinline__ uint32_t pack_lo(float a, float b) {
    __nv_bfloat16 ha = __float2bfloat16(a);
    __nv_bfloat16 hb = __float2bfloat16(b);
    return pack_bf16(__float2bfloat16(a - __bfloat162float(ha)),
                     __float2bfloat16(b - __bfloat162float(hb)));
}

static __device__ __forceinline__ uint32_t smem_u32(const void* p) {
    uint32_t a;
    asm("{ .reg .u64 t; cvta.to.shared.u64 t, %1; cvt.u32.u64 %0, t; }" : "=r"(a) : "l"(p));
    return a;
}

#define CP_ASYNC16(dst, src) \
    asm volatile("cp.async.ca.shared.global [%0], [%1], 16;" :: "r"(dst), "l"(src) : "memory")

__global__ void __launch_bounds__(NT, 3)
spconv_mma_kernel(const float* __restrict__ x,
                  const float* __restrict__ Wg,
                  const float* __restrict__ bias,
                  float* __restrict__ out) {
    __shared__ __align__(16) char smc[SMEM_TOT];
    const uint32_t sb = smem_u32(smc);

    const int tid = threadIdx.x;
    const long long p0 = (long long)blockIdx.x * TILE;
    const int b   = (int)(p0 / HW);
    const int hw0 = (int)(p0 % HW);
    const float* xb = x + (long long)b * CIN * HW + hw0;

    // ---- issue x staging FIRST: 4 coalesced cp.async.128 per thread ----
    #pragma unroll
    for (int it = 0; it < 4; ++it) {
        int i  = tid + it * NT;
        int ch = i >> 5;     // channel
        int q  = i & 31;     // pixel quad
        CP_ASYNC16(sb + XS_OFF + ch * XPITCHB + q * 16, xb + (long long)ch * HW + 4 * q);
    }
    asm volatile("cp.async.commit_group;" ::: "memory");

    // ---- stage W^T hi/lo (overlaps cp.async): thread -> (o, 2 slots) ----
    {
        const int o = tid >> 2;
        const int q = tid & 3;
        const int k = q >> 1;
        #pragma unroll
        for (int t2 = 0; t2 < 2; ++t2) {
            int t  = 2 * (q & 1) + t2;
            int ch0 = 2 * t + 16 * k;      // pair (ch0, ch0+1)
            int ch1 = ch0 + 8;             // pair (ch1, ch1+1)
            float a0 = Wg[ch0 * COUT + o], a1 = Wg[(ch0 + 1) * COUT + o];
            float b0 = Wg[ch1 * COUT + o], b1 = Wg[(ch1 + 1) * COUT + o];
            int off = o * WPITCHB + k * 32 + t * 8;
            *(uint2*)(smc + WHI_OFF + off) = make_uint2(pack_hi(a0, a1), pack_hi(b0, b1));
            *(uint2*)(smc + WLO_OFF + off) = make_uint2(pack_lo(a0, a1), pack_lo(b0, b1));
        }
    }
    if (tid < COUT) ((float*)(smc + BS_OFF))[tid] = bias[tid];

    // warp decomposition: wp = pixel quarter (32px), wo = output half (32 outs)
    const int w  = tid >> 5;
    const int wo = w >> 2;        // 0..1
    const int wp = w & 3;         // 0..3
    const int l  = tid & 31;
    const int g  = l >> 2;
    const int t  = l & 3;
    const int pxbase = 32 * wp;

    // ---- wait x staging, sync (also publishes W smem) ----
    asm volatile("cp.async.wait_group 0;" ::: "memory");
    __syncthreads();

    float acc[2][4][4];
    #pragma unroll
    for (int m = 0; m < 2; ++m)
        #pragma unroll
        for (int n = 0; n < 4; ++n)
            #pragma unroll
            for (int r = 0; r < 4; ++r) acc[m][n][r] = 0.0f;

    uint32_t msk[4] = {0u, 0u, 0u, 0u};   // px: pxbase+16m+g (+8)

    const char* xsm = smc + XS_OFF;
    const char* WH  = smc + WHI_OFF + (32 * wo) * WPITCHB;
    const char* WL  = smc + WLO_OFF + (32 * wo) * WPITCHB;

    // ---- mainloop: k-major (A frags live only per-k); 3-term bf16 split ----
    #pragma unroll
    for (int k = 0; k < 2; ++k) {
        uint32_t ah[2][4], al[2][4];
        #pragma unroll
        for (int m = 0; m < 2; ++m) {
            const int px0 = pxbase + 16 * m + g;
            const int ch0 = 2 * t + 16 * k;
            const int ch8 = ch0 + 8;
            float f00 = *(const float*)(xsm + ch0 * XPITCHB + px0 * 4);
            float f01 = *(const float*)(xsm + (ch0 + 1) * XPITCHB + px0 * 4);
            float f10 = *(const float*)(xsm + ch0 * XPITCHB + (px0 + 8) * 4);
            float f11 = *(const float*)(xsm + (ch0 + 1) * XPITCHB + (px0 + 8) * 4);
            float f20 = *(const float*)(xsm + ch8 * XPITCHB + px0 * 4);
            float f21 = *(const float*)(xsm + (ch8 + 1) * XPITCHB + px0 * 4);
            float f30 = *(const float*)(xsm + ch8 * XPITCHB + (px0 + 8) * 4);
            float f31 = *(const float*)(xsm + (ch8 + 1) * XPITCHB + (px0 + 8) * 4);

            msk[2 * m]     |= (__float_as_uint(f00) | __float_as_uint(f01) |
                               __float_as_uint(f20) | __float_as_uint(f21)) & 0x7FFFFFFFu;
            msk[2 * m + 1] |= (__float_as_uint(f10) | __float_as_uint(f11) |
                               __float_as_uint(f30) | __float_as_uint(f31)) & 0x7FFFFFFFu;

            ah[m][0] = pack_hi(f00, f01);  ah[m][1] = pack_hi(f10, f11);
            ah[m][2] = pack_hi(f20, f21);  ah[m][3] = pack_hi(f30, f31);
            al[m][0] = pack_lo(f00, f01);  al[m][1] = pack_lo(f10, f11);
            al[m][2] = pack_lo(f20, f21);  al[m][3] = pack_lo(f30, f31);
        }

        #pragma unroll
        for (int nb = 0; nb < 2; ++nb) {
            uint32_t bh[2][2], bl[2][2];
            #pragma unroll
            for (int nn = 0; nn < 2; ++nn) {
                int off = (8 * (2 * nb + nn) + g) * WPITCHB + k * 32 + t * 8;  // FIX: +g
                uint2 hv = *(const uint2*)(WH + off);
                uint2 lv = *(const uint2*)(WL + off);
                bh[nn][0] = hv.x; bh[nn][1] = hv.y;
                bl[nn][0] = lv.x; bl[nn][1] = lv.y;
            }
            #pragma unroll
            for (int nn = 0; nn < 2; ++nn)
                #pragma unroll
                for (int m = 0; m < 2; ++m)
                    mma16816(acc[m][2 * nb + nn], ah[m], bh[nn]);
            #pragma unroll
            for (int nn = 0; nn < 2; ++nn)
                #pragma unroll
                for (int m = 0; m < 2; ++m)
                    mma16816(acc[m][2 * nb + nn], ah[m], bl[nn]);
            #pragma unroll
            for (int nn = 0; nn < 2; ++nn)
                #pragma unroll
                for (int m = 0; m < 2; ++m)
                    mma16816(acc[m][2 * nb + nn], al[m], bh[nn]);
        }
    }

    // msk currently: per-thread OR of its 8 chans; combine across t-quad
    #pragma unroll
    for (int r = 0; r < 4; ++r) {
        msk[r] |= __shfl_xor_sync(0xFFFFFFFFu, msk[r], 1);
        msk[r] |= __shfl_xor_sync(0xFFFFFFFFu, msk[r], 2);
    }

    // ---- epilogue: direct masked STG (proven-best store path) ----
    const float* bs = (const float*)(smc + BS_OFF);
    float* ob = out + (long long)b * COUT * HW + hw0;
    #pragma unroll
    for (int m = 0; m < 2; ++m) {
        int px0 = pxbase + 16 * m + g;
        int px1 = px0 + 8;
        bool A0 = msk[2 * m]     != 0u;
        bool A1 = msk[2 * m + 1] != 0u;
        #pragma unroll
        for (int n = 0; n < 4; ++n) {
            int o = 32 * wo + 8 * n + 2 * t;
            float2 bv = *(const float2*)(bs + o);
            ob[(long long)o * HW + px0]       = A0 ? acc[m][n][0] + bv.x : 0.0f;
            ob[(long long)(o + 1) * HW + px0] = A0 ? acc[m][n][1] + bv.y : 0.0f;
            ob[(long long)o * HW + px1]       = A1 ? acc[m][n][2] + bv.x : 0.0f;
            ob[(long long)(o + 1) * HW + px1] = A1 ? acc[m][n][3] + bv.y : 0.0f;
        }
    }
}

extern "C" void kernel_launch(void* const* d_in, const int* in_sizes, int n_in,
                              void* d_out, int out_size) {
    const float* x  = (const float*)d_in[0];
    const float* Wg = (const float*)d_in[1];
    const float* bi = (const float*)d_in[2];
    float* out = (float*)d_out;

    const int grid = NPIX / TILE;   // 16384
    spconv_mma_kernel<<<grid, NT>>>(x, Wg, bi, out);
}